// round 2
// baseline (speedup 1.0000x reference)
#include <cuda_runtime.h>

// glb_pos [B,T,J,3], glb_rot [B,T,J,4], glb_vel [B,T-1,J,3], root_rotation [B,T,1,4]
// Output: pos_out [B,T,J,3] followed by rot_out [B,T,J,4], float32.

#define MAX_B 64
#define MAX_T 1024
#define GSLICE 4          // blocks per batch in the fused kernel

__device__ float3 g_traj[MAX_B * MAX_T];   // fallback-path scratch

struct Q { float w, x, y, z; };

__device__ __forceinline__ Q qmul(Q a, Q b) {
    Q r;
    r.w = a.w * b.w - a.x * b.x - a.y * b.y - a.z * b.z;
    r.x = a.w * b.x + a.x * b.w + a.y * b.z - a.z * b.y;
    r.y = a.w * b.y - a.x * b.z + a.y * b.w + a.z * b.x;
    r.z = a.w * b.z + a.x * b.y - a.y * b.x + a.z * b.w;
    return r;
}

__device__ __forceinline__ float3 qapply(Q q, float3 p) {
    Q pq; pq.w = 0.f; pq.x = p.x; pq.y = p.y; pq.z = p.z;
    Q t = qmul(q, pq);
    Q c; c.w = q.w; c.x = -q.x; c.y = -q.y; c.z = -q.z;
    Q r = qmul(t, c);
    return make_float3(r.x, r.y, r.z);
}

__device__ __forceinline__ Q load_inv(const float4* __restrict__ root, int idx) {
    float4 v = __ldg(root + idx);                        // (w,x,y,z) real-first
    Q q; q.w = v.x; q.x = -v.y; q.y = -v.z; q.z = -v.w;  // conjugate
    return q;
}

// ---------------------------------------------------------------------------
// Fused kernel (specialized: J==32, T==1024, blockDim==1024).
// Grid = B*GSLICE. Each block:
//   Phase 1: full block-wide scan of rotated joint-0 velocities for batch b
//            -> trajectory (x,z) in shared memory (redundant across the
//            GSLICE blocks of a batch; input is tiny and L2-hot).
//   Phase 2: elementwise quaternion work for its T/GSLICE time-slice.
//            warp = time step, lane = joint (J==32). No integer divides.
// ---------------------------------------------------------------------------
__global__ void __launch_bounds__(1024, 1) fused_kernel(
    const float* __restrict__ glb_pos,
    const float4* __restrict__ glb_rot,
    const float* __restrict__ glb_vel,
    const float4* __restrict__ root,
    float* __restrict__ out_pos,
    float4* __restrict__ out_rot)
{
    const int T = 1024, J = 32;
    __shared__ float2 s_traj[1024];
    __shared__ float3 s_wsum[32];
    __shared__ float3 s_pos0;

    const int b     = blockIdx.x >> 2;          // / GSLICE
    const int slice = blockIdx.x & (GSLICE - 1);
    const int t     = threadIdx.x;
    const int lane  = t & 31, warp = t >> 5;

    // ---------------- Phase 1: trajectory scan ----------------
    Q inv = load_inv(root, b * T + t);

    float3 v = make_float3(0.f, 0.f, 0.f);
    if (t < T - 1) {
        const float* vp = glb_vel + ((b * (T - 1) + t) * J) * 3;  // joint 0
        float3 p = make_float3(__ldg(vp), __ldg(vp + 1), __ldg(vp + 2));
        v = qapply(inv, p);
    }
    if (t == 0) {
        const float* pp = glb_pos + (long)b * T * J * 3;
        float3 p = make_float3(__ldg(pp), __ldg(pp + 1), __ldg(pp + 2));
        s_pos0 = qapply(inv, p);
    }

    // warp inclusive scan
    float3 s = v;
    #pragma unroll
    for (int o = 1; o < 32; o <<= 1) {
        float ax = __shfl_up_sync(0xFFFFFFFFu, s.x, o);
        float ay = __shfl_up_sync(0xFFFFFFFFu, s.y, o);
        float az = __shfl_up_sync(0xFFFFFFFFu, s.z, o);
        if (lane >= o) { s.x += ax; s.y += ay; s.z += az; }
    }
    if (lane == 31) s_wsum[warp] = s;
    __syncthreads();
    if (warp == 0) {
        float3 ws = s_wsum[lane];
        #pragma unroll
        for (int o = 1; o < 32; o <<= 1) {
            float ax = __shfl_up_sync(0xFFFFFFFFu, ws.x, o);
            float ay = __shfl_up_sync(0xFFFFFFFFu, ws.y, o);
            float az = __shfl_up_sync(0xFFFFFFFFu, ws.z, o);
            if (lane >= o) { ws.x += ax; ws.y += ay; ws.z += az; }
        }
        s_wsum[lane] = ws;
    }
    __syncthreads();

    float3 prefix = (warp > 0) ? s_wsum[warp - 1] : make_float3(0.f, 0.f, 0.f);
    float3 incl = make_float3(s.x + prefix.x, s.y + prefix.y, s.z + prefix.z);
    float3 excl;
    excl.x = __shfl_up_sync(0xFFFFFFFFu, incl.x, 1);
    excl.y = __shfl_up_sync(0xFFFFFFFFu, incl.y, 1);
    excl.z = __shfl_up_sync(0xFFFFFFFFu, incl.z, 1);
    if (lane == 0) excl = prefix;
    __syncthreads();   // s_pos0 visible

    s_traj[t] = make_float2(s_pos0.x + excl.x, s_pos0.z + excl.z);
    __syncthreads();

    // ---------------- Phase 2: elementwise slice ----------------
    const int t0 = slice * (T / GSLICE);        // 256 timesteps per slice
    #pragma unroll 2
    for (int i = 0; i < (T / GSLICE) / 32; ++i) {   // 8 iterations
        const int tt  = t0 + i * 32 + warp;
        const int bt  = b * T + tt;
        const int idx = bt * 32 + lane;             // (b,t,j) flat, J==32

        Q qi = load_inv(root, bt);                  // warp-uniform, L1 broadcast

        const float* pp = glb_pos + idx * 3;
        float3 p = make_float3(__ldg(pp), __ldg(pp + 1), __ldg(pp + 2));
        float4 r4 = __ldg(glb_rot + idx);
        float2 tr = s_traj[tt];

        float3 pr = qapply(qi, p);
        float* po = out_pos + idx * 3;
        po[0] = pr.x + tr.x;
        po[1] = pr.y;                               // xz mask: no traj on y
        po[2] = pr.z + tr.y;

        Q r; r.w = r4.x; r.x = r4.y; r.y = r4.z; r.z = r4.w;
        Q m = qmul(qi, r);
        if (m.w < 0.f) { m.w = -m.w; m.x = -m.x; m.y = -m.y; m.z = -m.z; }
        out_rot[idx] = make_float4(m.w, m.x, m.y, m.z);
    }
}

// ---------------------------------------------------------------------------
// Fallback path (generic dims): previous 2-kernel implementation.
// ---------------------------------------------------------------------------
__global__ void __launch_bounds__(1024) traj_kernel(
    const float* __restrict__ glb_pos,
    const float* __restrict__ glb_vel,
    const float4* __restrict__ root,
    int T, int J)
{
    const int b = blockIdx.x;
    const int t = threadIdx.x;
    const int lane = t & 31, warp = t >> 5;
    __shared__ float3 s_wsum[32];
    __shared__ float3 s_pos0;
    if (t >= T) return;

    Q inv = load_inv(root, b * T + t);
    float3 v = make_float3(0.f, 0.f, 0.f);
    if (t < T - 1) {
        const float* vp = glb_vel + ((long)(b * (T - 1) + t) * J) * 3;
        v = qapply(inv, make_float3(__ldg(vp), __ldg(vp + 1), __ldg(vp + 2)));
    }
    if (t == 0) {
        const float* pp = glb_pos + (long)b * T * J * 3;
        s_pos0 = qapply(inv, make_float3(__ldg(pp), __ldg(pp + 1), __ldg(pp + 2)));
    }
    float3 s = v;
    #pragma unroll
    for (int o = 1; o < 32; o <<= 1) {
        float ax = __shfl_up_sync(0xFFFFFFFFu, s.x, o);
        float ay = __shfl_up_sync(0xFFFFFFFFu, s.y, o);
        float az = __shfl_up_sync(0xFFFFFFFFu, s.z, o);
        if (lane >= o) { s.x += ax; s.y += ay; s.z += az; }
    }
    if (lane == 31) s_wsum[warp] = s;
    __syncthreads();
    if (warp == 0) {
        float3 ws = s_wsum[lane];
        #pragma unroll
        for (int o = 1; o < 32; o <<= 1) {
            float ax = __shfl_up_sync(0xFFFFFFFFu, ws.x, o);
            float ay = __shfl_up_sync(0xFFFFFFFFu, ws.y, o);
            float az = __shfl_up_sync(0xFFFFFFFFu, ws.z, o);
            if (lane >= o) { ws.x += ax; ws.y += ay; ws.z += az; }
        }
        s_wsum[lane] = ws;
    }
    __syncthreads();
    float3 prefix = (warp > 0) ? s_wsum[warp - 1] : make_float3(0.f, 0.f, 0.f);
    float3 incl = make_float3(s.x + prefix.x, s.y + prefix.y, s.z + prefix.z);
    float3 excl;
    excl.x = __shfl_up_sync(0xFFFFFFFFu, incl.x, 1);
    excl.y = __shfl_up_sync(0xFFFFFFFFu, incl.y, 1);
    excl.z = __shfl_up_sync(0xFFFFFFFFu, incl.z, 1);
    if (lane == 0) excl = prefix;
    float3 p0 = s_pos0;
    g_traj[b * T + t] = make_float3(p0.x + excl.x, 0.f, p0.z + excl.z);
}

__global__ void __launch_bounds__(256) main_kernel(
    const float* __restrict__ glb_pos,
    const float4* __restrict__ glb_rot,
    const float4* __restrict__ root,
    float* __restrict__ out_pos,
    float4* __restrict__ out_rot,
    int T, int J, int total)
{
    int idx = blockIdx.x * blockDim.x + threadIdx.x;
    if (idx >= total) return;
    int tj = T * J;
    int b = idx / tj;
    int t = (idx - b * tj) / J;

    Q inv = load_inv(root, b * T + t);
    long pbase = (long)idx * 3;
    float3 p = make_float3(__ldg(glb_pos + pbase), __ldg(glb_pos + pbase + 1),
                           __ldg(glb_pos + pbase + 2));
    float3 pr = qapply(inv, p);
    float3 tr = g_traj[b * T + t];
    out_pos[pbase]     = pr.x + tr.x;
    out_pos[pbase + 1] = pr.y;
    out_pos[pbase + 2] = pr.z + tr.z;

    float4 r4 = __ldg(glb_rot + idx);
    Q r; r.w = r4.x; r.x = r4.y; r.y = r4.z; r.z = r4.w;
    Q m = qmul(inv, r);
    if (m.w < 0.f) { m.w = -m.w; m.x = -m.x; m.y = -m.y; m.z = -m.z; }
    out_rot[idx] = make_float4(m.w, m.x, m.y, m.z);
}

extern "C" void kernel_launch(void* const* d_in, const int* in_sizes, int n_in,
                              void* d_out, int out_size)
{
    const float* glb_pos = (const float*)d_in[0];   // B*T*J*3
    const float* glb_rot = (const float*)d_in[1];   // B*T*J*4
    const float* glb_vel = (const float*)d_in[2];   // B*(T-1)*J*3
    const float* root    = (const float*)d_in[3];   // B*T*4

    int J = (int)((4LL * in_sizes[0]) / (3LL * in_sizes[3]));
    int B = (in_sizes[0] - in_sizes[2]) / (3 * J);
    int T = in_sizes[3] / (4 * B);
    int total = B * T * J;

    float*  out_pos = (float*)d_out;
    float4* out_rot = (float4*)((float*)d_out + (long)total * 3);

    if (J == 32 && T == 1024 && B <= MAX_B) {
        fused_kernel<<<B * GSLICE, 1024>>>(glb_pos, (const float4*)glb_rot,
                                           glb_vel, (const float4*)root,
                                           out_pos, out_rot);
    } else {
        traj_kernel<<<B, T>>>(glb_pos, glb_vel, (const float4*)root, T, J);
        int threads = 256;
        int blocks = (total + threads - 1) / threads;
        main_kernel<<<blocks, threads>>>(glb_pos, (const float4*)glb_rot,
                                         (const float4*)root,
                                         out_pos, out_rot, T, J, total);
    }
}

// round 3
// speedup vs baseline: 1.0703x; 1.0703x over previous
#include <cuda_runtime.h>

// glb_pos [B,T,J,3], glb_rot [B,T,J,4], glb_vel [B,T-1,J,3], root_rotation [B,T,1,4]
// Output: pos_out [B,T,J,3] then rot_out [B,T,J,4], float32.

#define MAX_B 64
#define MAX_T 1024

__device__ float2 g_traj2[MAX_B * MAX_T];  // fast path: (x,z) trajectory
__device__ float3 g_traj[MAX_B * MAX_T];   // fallback path scratch

struct Q { float w, x, y, z; };

__device__ __forceinline__ Q qmul(Q a, Q b) {
    Q r;
    r.w = a.w * b.w - a.x * b.x - a.y * b.y - a.z * b.z;
    r.x = a.w * b.x + a.x * b.w + a.y * b.z - a.z * b.y;
    r.y = a.w * b.y - a.x * b.z + a.y * b.w + a.z * b.x;
    r.z = a.w * b.z + a.x * b.y - a.y * b.x + a.z * b.w;
    return r;
}

__device__ __forceinline__ float3 qapply(Q q, float3 p) {
    Q pq; pq.w = 0.f; pq.x = p.x; pq.y = p.y; pq.z = p.z;
    Q t = qmul(q, pq);
    Q c; c.w = q.w; c.x = -q.x; c.y = -q.y; c.z = -q.z;
    Q r = qmul(t, c);
    return make_float3(r.x, r.y, r.z);
}

__device__ __forceinline__ Q load_inv(const float4* __restrict__ root, int idx) {
    float4 v = __ldg(root + idx);                        // (w,x,y,z) real-first
    Q q; q.w = v.x; q.x = -v.y; q.y = -v.z; q.z = -v.w;  // conjugate
    return q;
}

// ===========================================================================
// FAST PATH (J==32, T==1024): two kernels, both 256-thread blocks, 128-bit IO.
//
// Kernel A: blocks [0,64) -> per-batch trajectory scan into g_traj2 (tiny,
//           hidden); blocks [64,...) -> full rot path (independent of traj).
// Kernel B: pos path, 4 elements/thread, reads g_traj2.
// ===========================================================================

__global__ void __launch_bounds__(256) kernelA(
    const float* __restrict__ glb_pos,
    const float4* __restrict__ glb_rot,
    const float* __restrict__ glb_vel,
    const float4* __restrict__ root,
    float4* __restrict__ out_rot,
    int total4)                       // total elements / 4
{
    if (blockIdx.x < 64) {
        // -------- trajectory scan for batch b (256 threads, 4 t each) ------
        const int T = 1024, J = 32;
        const int b = blockIdx.x;
        const int t4 = threadIdx.x;                 // 0..255
        const int lane = t4 & 31, warp = t4 >> 5;   // 8 warps
        __shared__ float3 s_ws[8];
        __shared__ float3 s_pos0;

        float3 vr[4];                 // per-thread inclusive partials
        float3 acc = make_float3(0.f, 0.f, 0.f);
        #pragma unroll
        for (int k = 0; k < 4; ++k) {
            int t = t4 * 4 + k;
            Q inv = load_inv(root, b * T + t);
            float3 v = make_float3(0.f, 0.f, 0.f);
            if (t < T - 1) {
                const float* vp = glb_vel + ((b * (T - 1) + t) * J) * 3; // joint 0
                v = qapply(inv, make_float3(__ldg(vp), __ldg(vp + 1), __ldg(vp + 2)));
            }
            if (t == 0) {
                const float* pp = glb_pos + (long)b * T * J * 3;
                s_pos0 = qapply(inv, make_float3(__ldg(pp), __ldg(pp + 1), __ldg(pp + 2)));
            }
            acc.x += v.x; acc.y += v.y; acc.z += v.z;
            vr[k] = acc;
        }

        // block scan of per-thread totals (acc)
        float3 s = acc;
        #pragma unroll
        for (int o = 1; o < 32; o <<= 1) {
            float ax = __shfl_up_sync(0xFFFFFFFFu, s.x, o);
            float ay = __shfl_up_sync(0xFFFFFFFFu, s.y, o);
            float az = __shfl_up_sync(0xFFFFFFFFu, s.z, o);
            if (lane >= o) { s.x += ax; s.y += ay; s.z += az; }
        }
        if (lane == 31) s_ws[warp] = s;
        __syncthreads();
        if (warp == 0 && lane < 8) {
            float3 ws = s_ws[lane];
            #pragma unroll
            for (int o = 1; o < 8; o <<= 1) {
                float ax = __shfl_up_sync(0x000000FFu, ws.x, o);
                float ay = __shfl_up_sync(0x000000FFu, ws.y, o);
                float az = __shfl_up_sync(0x000000FFu, ws.z, o);
                if (lane >= o) { ws.x += ax; ws.y += ay; ws.z += az; }
            }
            s_ws[lane] = ws;
        }
        __syncthreads();

        float3 wpre = (warp > 0) ? s_ws[warp - 1] : make_float3(0.f, 0.f, 0.f);
        float3 incl = make_float3(s.x + wpre.x, s.y + wpre.y, s.z + wpre.z);
        // exclusive for this thread: shift inclusive down one lane
        float3 excl;
        excl.x = __shfl_up_sync(0xFFFFFFFFu, incl.x, 1);
        excl.y = __shfl_up_sync(0xFFFFFFFFu, incl.y, 1);
        excl.z = __shfl_up_sync(0xFFFFFFFFu, incl.z, 1);
        if (lane == 0) excl = wpre;

        float3 p0 = s_pos0;
        #pragma unroll
        for (int k = 0; k < 4; ++k) {
            float ex = excl.x, ez = excl.z;
            if (k > 0) { ex += vr[k - 1].x; ez += vr[k - 1].z; }
            g_traj2[b * T + t4 * 4 + k] = make_float2(p0.x + ex, p0.z + ez);
        }
    } else {
        // -------- rot path: 4 elements per thread, all 128-bit IO ----------
        int tid4 = (blockIdx.x - 64) * 256 + threadIdx.x;
        if (tid4 >= total4) return;
        int bt = tid4 >> 3;                          // 8 threads per (b,t) row
        Q inv = load_inv(root, bt);
        const float4* rin = glb_rot + tid4 * 4;
        #pragma unroll
        for (int k = 0; k < 4; ++k) {
            float4 r4 = __ldg(rin + k);
            Q r; r.w = r4.x; r.x = r4.y; r.y = r4.z; r.z = r4.w;
            Q m = qmul(inv, r);
            if (m.w < 0.f) { m.w = -m.w; m.x = -m.x; m.y = -m.y; m.z = -m.z; }
            out_rot[tid4 * 4 + k] = make_float4(m.w, m.x, m.y, m.z);
        }
    }
}

__global__ void __launch_bounds__(256) kernelB(
    const float4* __restrict__ glb_pos4,
    const float4* __restrict__ root,
    float4* __restrict__ out_pos4,
    int total4)
{
    int tid4 = blockIdx.x * 256 + threadIdx.x;
    if (tid4 >= total4) return;
    int bt = tid4 >> 3;

    Q inv = load_inv(root, bt);
    float2 tr = g_traj2[bt];

    const float4* pin = glb_pos4 + tid4 * 3;         // 48B per thread, aligned
    float4 a = __ldg(pin);
    float4 b = __ldg(pin + 1);
    float4 c = __ldg(pin + 2);

    float3 r0 = qapply(inv, make_float3(a.x, a.y, a.z));
    float3 r1 = qapply(inv, make_float3(a.w, b.x, b.y));
    float3 r2 = qapply(inv, make_float3(b.z, b.w, c.x));
    float3 r3 = qapply(inv, make_float3(c.y, c.z, c.w));

    float4* po = out_pos4 + tid4 * 3;
    po[0] = make_float4(r0.x + tr.x, r0.y, r0.z + tr.y, r1.x + tr.x);
    po[1] = make_float4(r1.y, r1.z + tr.y, r2.x + tr.x, r2.y);
    po[2] = make_float4(r2.z + tr.y, r3.x + tr.x, r3.y, r3.z + tr.y);
}

// ===========================================================================
// Fallback (generic dims): R1's proven two-kernel path.
// ===========================================================================
__global__ void __launch_bounds__(1024) traj_kernel(
    const float* __restrict__ glb_pos,
    const float* __restrict__ glb_vel,
    const float4* __restrict__ root,
    int T, int J)
{
    const int b = blockIdx.x;
    const int t = threadIdx.x;
    const int lane = t & 31, warp = t >> 5;
    __shared__ float3 s_wsum[32];
    __shared__ float3 s_pos0;
    if (t >= T) return;

    Q inv = load_inv(root, b * T + t);
    float3 v = make_float3(0.f, 0.f, 0.f);
    if (t < T - 1) {
        const float* vp = glb_vel + ((long)(b * (T - 1) + t) * J) * 3;
        v = qapply(inv, make_float3(__ldg(vp), __ldg(vp + 1), __ldg(vp + 2)));
    }
    if (t == 0) {
        const float* pp = glb_pos + (long)b * T * J * 3;
        s_pos0 = qapply(inv, make_float3(__ldg(pp), __ldg(pp + 1), __ldg(pp + 2)));
    }
    float3 s = v;
    #pragma unroll
    for (int o = 1; o < 32; o <<= 1) {
        float ax = __shfl_up_sync(0xFFFFFFFFu, s.x, o);
        float ay = __shfl_up_sync(0xFFFFFFFFu, s.y, o);
        float az = __shfl_up_sync(0xFFFFFFFFu, s.z, o);
        if (lane >= o) { s.x += ax; s.y += ay; s.z += az; }
    }
    if (lane == 31) s_wsum[warp] = s;
    __syncthreads();
    if (warp == 0) {
        float3 ws = s_wsum[lane];
        #pragma unroll
        for (int o = 1; o < 32; o <<= 1) {
            float ax = __shfl_up_sync(0xFFFFFFFFu, ws.x, o);
            float ay = __shfl_up_sync(0xFFFFFFFFu, ws.y, o);
            float az = __shfl_up_sync(0xFFFFFFFFu, ws.z, o);
            if (lane >= o) { ws.x += ax; ws.y += ay; ws.z += az; }
        }
        s_wsum[lane] = ws;
    }
    __syncthreads();
    float3 prefix = (warp > 0) ? s_wsum[warp - 1] : make_float3(0.f, 0.f, 0.f);
    float3 incl = make_float3(s.x + prefix.x, s.y + prefix.y, s.z + prefix.z);
    float3 excl;
    excl.x = __shfl_up_sync(0xFFFFFFFFu, incl.x, 1);
    excl.y = __shfl_up_sync(0xFFFFFFFFu, incl.y, 1);
    excl.z = __shfl_up_sync(0xFFFFFFFFu, incl.z, 1);
    if (lane == 0) excl = prefix;
    float3 p0 = s_pos0;
    g_traj[b * T + t] = make_float3(p0.x + excl.x, 0.f, p0.z + excl.z);
}

__global__ void __launch_bounds__(256) main_kernel(
    const float* __restrict__ glb_pos,
    const float4* __restrict__ glb_rot,
    const float4* __restrict__ root,
    float* __restrict__ out_pos,
    float4* __restrict__ out_rot,
    int T, int J, int total)
{
    int idx = blockIdx.x * blockDim.x + threadIdx.x;
    if (idx >= total) return;
    int tj = T * J;
    int b = idx / tj;
    int t = (idx - b * tj) / J;

    Q inv = load_inv(root, b * T + t);
    long pbase = (long)idx * 3;
    float3 p = make_float3(__ldg(glb_pos + pbase), __ldg(glb_pos + pbase + 1),
                           __ldg(glb_pos + pbase + 2));
    float3 pr = qapply(inv, p);
    float3 tr = g_traj[b * T + t];
    out_pos[pbase]     = pr.x + tr.x;
    out_pos[pbase + 1] = pr.y;
    out_pos[pbase + 2] = pr.z + tr.z;

    float4 r4 = __ldg(glb_rot + idx);
    Q r; r.w = r4.x; r.x = r4.y; r.y = r4.z; r.z = r4.w;
    Q m = qmul(inv, r);
    if (m.w < 0.f) { m.w = -m.w; m.x = -m.x; m.y = -m.y; m.z = -m.z; }
    out_rot[idx] = make_float4(m.w, m.x, m.y, m.z);
}

extern "C" void kernel_launch(void* const* d_in, const int* in_sizes, int n_in,
                              void* d_out, int out_size)
{
    const float* glb_pos = (const float*)d_in[0];   // B*T*J*3
    const float* glb_rot = (const float*)d_in[1];   // B*T*J*4
    const float* glb_vel = (const float*)d_in[2];   // B*(T-1)*J*3
    const float* root    = (const float*)d_in[3];   // B*T*4

    int J = (int)((4LL * in_sizes[0]) / (3LL * in_sizes[3]));
    int B = (in_sizes[0] - in_sizes[2]) / (3 * J);
    int T = in_sizes[3] / (4 * B);
    int total = B * T * J;

    float*  out_pos = (float*)d_out;
    float4* out_rot = (float4*)((float*)d_out + (long)total * 3);

    if (J == 32 && T == 1024 && B == 64 && (total % 4 == 0)) {
        int total4 = total / 4;                       // 524288
        int rot_blocks = (total4 + 255) / 256;        // 2048
        kernelA<<<64 + rot_blocks, 256>>>(glb_pos, (const float4*)glb_rot,
                                          glb_vel, (const float4*)root,
                                          out_rot, total4);
        kernelB<<<(total4 + 255) / 256, 256>>>((const float4*)glb_pos,
                                               (const float4*)root,
                                               (float4*)out_pos, total4);
    } else {
        traj_kernel<<<B, T>>>(glb_pos, glb_vel, (const float4*)root, T, J);
        int threads = 256;
        int blocks = (total + threads - 1) / threads;
        main_kernel<<<blocks, threads>>>(glb_pos, (const float4*)glb_rot,
                                         (const float4*)root,
                                         out_pos, out_rot, T, J, total);
    }
}